// round 16
// baseline (speedup 1.0000x reference)
#include <cuda_runtime.h>
#include <cuda_fp16.h>
#include <math.h>
#include <cstdint>

// Problem constants
#define Bsz 2
#define SQd 256
#define SKd 512
#define Ed  512
#define Hd  256

#define NQ (Bsz*SQd)   // 512
#define NK (Bsz*SKd)   // 1024
#define OFF_QF 0
#define OFF_KF (OFF_QF + NQ*Hd)
#define OFF_QP (OFF_KF + NK*Hd)
#define OFF_KP (OFF_QP + NQ*Hd)
#define OFF_QV (OFF_KP + NK*Hd)
#define OFF_KV (OFF_QV + NQ*Hd)
#define SCRATCH_FLOATS (OFF_KV + NK*Hd)

__device__ float g_scratch[SCRATCH_FLOATS];
// Transposed fp16 weights: [W1h][W2h], each [256 n][256 k]
__device__ __align__(16) __half g_wt[2 * 256 * 256];

__device__ __forceinline__ float frelu(float x) { return x > 0.f ? x : 0.f; }
__device__ __forceinline__ float4 ldg4(const float* p) { return __ldg((const float4*)p); }

__device__ __forceinline__ uint32_t smem_to_u32(const void* p) {
    uint32_t a;
    asm("{ .reg .u64 t; cvta.to.shared.u64 t, %1; cvt.u32.u64 %0, t; }" : "=r"(a) : "l"(p));
    return a;
}
__device__ __forceinline__ void cp16(uint32_t dst, const void* src) {
    asm volatile("cp.async.cg.shared.global [%0], [%1], 16;" :: "r"(dst), "l"(src));
}
#define CP_COMMIT() asm volatile("cp.async.commit_group;" ::: "memory")
#define CP_WAIT0()  asm volatile("cp.async.wait_group 0;" ::: "memory")

// fp16 inputs, fp32 accumulate
__device__ __forceinline__ void mma_f32acc(float* c, const uint32_t* a, const uint32_t* b) {
    asm volatile(
        "mma.sync.aligned.m16n8k16.row.col.f32.f16.f16.f32 "
        "{%0,%1,%2,%3}, {%4,%5,%6,%7}, {%8,%9}, {%0,%1,%2,%3};"
        : "+f"(c[0]), "+f"(c[1]), "+f"(c[2]), "+f"(c[3])
        : "r"(a[0]), "r"(a[1]), "r"(a[2]), "r"(a[3]), "r"(b[0]), "r"(b[1]));
}
__device__ __forceinline__ void ldsm4(uint32_t* r, uint32_t addr) {
    asm volatile("ldmatrix.sync.aligned.m8n8.x4.shared.b16 {%0,%1,%2,%3}, [%4];"
                 : "=r"(r[0]), "=r"(r[1]), "=r"(r[2]), "=r"(r[3]) : "r"(addr));
}
// pack two fp32 -> fp16x2
__device__ __forceinline__ uint32_t pack2h(float x0, float x1) {
    __half2 p = __floats2half2_rn(x0, x1);
    return *reinterpret_cast<uint32_t*>(&p);
}

// ---------------------------------------------------------------------------
// Prep GEMM tile v2: 16 rows x 64 cols per block, 256 threads, 1x4 outputs.
// cp.async double-buffered. More blocks -> TLP hides LDS/FFMA latency.
// ---------------------------------------------------------------------------
#define ASP 36   // As row pitch (floats): mult of 4 (float4 stores), kills bank conflict
__device__ void gemm_tile16(const float* __restrict__ A,
                            const float* __restrict__ W,
                            const float* __restrict__ bias,
                            float* __restrict__ C,
                            int K, int act, int row0, int col0)
{
    __shared__ float As[2][16 * ASP];
    __shared__ float Ws[2][32 * 64];
    const int tid = threadIdx.x;
    const int tr  = tid >> 4;          // 0..15 -> row
    const int tc  = tid & 15;          // 0..15 -> cols tc*4..+3
    const uint32_t as0 = smem_to_u32(As);
    const uint32_t ws0 = smem_to_u32(Ws);

    // A loaders: threads 0..127, r = tid>>3 (0..15), ck = (tid&7)*4
    const int alr  = tid >> 3;
    const int alck = (tid & 7) * 4;
    const bool aload = tid < 128;

    // prefetch chunk 0
    if (aload)
        cp16(as0 + (uint32_t)(alr * ASP + alck) * 4, A + (size_t)(row0 + alr) * K + alck);
    #pragma unroll
    for (int i = 0; i < 2; i++) {
        int f = tid + 256 * i; int k = f >> 4; int cc = (f & 15) * 4;
        cp16(ws0 + (uint32_t)(k * 64 + cc) * 4, W + (size_t)k * 256 + col0 + cc);
    }
    CP_COMMIT();

    float ax = 0.f, ay = 0.f, az = 0.f, aw = 0.f;
    if (bias) {
        float4 bb = ldg4(bias + col0 + tc * 4);
        ax = bb.x; ay = bb.y; az = bb.z; aw = bb.w;
    }

    const int nch = K >> 5;
    for (int g = 0; g < nch; g++) {
        CP_WAIT0();
        __syncthreads();
        if (g + 1 < nch) {
            int kc = (g + 1) * 32;
            uint32_t bsel = (uint32_t)((g + 1) & 1);
            if (aload)
                cp16(as0 + bsel * (16 * ASP * 4) + (uint32_t)(alr * ASP + alck) * 4,
                     A + (size_t)(row0 + alr) * K + kc + alck);
            #pragma unroll
            for (int i = 0; i < 2; i++) {
                int f = tid + 256 * i; int k = f >> 4; int cc = (f & 15) * 4;
                cp16(ws0 + bsel * 8192 + (uint32_t)(k * 64 + cc) * 4,
                     W + (size_t)(kc + k) * 256 + col0 + cc);
            }
            CP_COMMIT();
        }
        const float* Asb = As[g & 1];
        const float* Wsb = Ws[g & 1];
        #pragma unroll
        for (int k = 0; k < 32; k++) {
            float a0 = Asb[tr * ASP + k];
            float4 w = *(const float4*)(Wsb + k * 64 + tc * 4);
            ax = fmaf(a0, w.x, ax); ay = fmaf(a0, w.y, ay);
            az = fmaf(a0, w.z, az); aw = fmaf(a0, w.w, aw);
        }
    }
    if (act) { ax = frelu(ax); ay = frelu(ay); az = frelu(az); aw = frelu(aw); }
    *(float4*)(C + (size_t)(row0 + tr) * 256 + col0 + tc * 4) =
        make_float4(ax, ay, az, aw);
}

// Launch 1: both encoders. grid (4, 96): y<32 -> qf rows, else kf rows
__global__ void encoder_kernel(const float* __restrict__ query,
                               const float* __restrict__ key_,
                               const float* __restrict__ Wqe, const float* __restrict__ bqe,
                               const float* __restrict__ Wke, const float* __restrict__ bke)
{
    float* S = g_scratch;
    int y = blockIdx.y;
    if (y < 32)
        gemm_tile16(query, Wqe, bqe, S + OFF_QF, Ed, 1, y * 16, blockIdx.x * 64);
    else
        gemm_tile16(key_,  Wke, bke, S + OFF_KF, Ed, 1, (y - 32) * 16, blockIdx.x * 64);
}

// Launch 2: 4 projections (b0 folded into qp, bv1 into qv) + W transpose (fp16).
// grid (4, 64, 5)
__global__ void proj_trans_kernel(const float* __restrict__ W0,
                                  const float* __restrict__ Wv1,
                                  const float* __restrict__ W1,
                                  const float* __restrict__ W2,
                                  const float* __restrict__ b0,
                                  const float* __restrict__ bv1)
{
    float* S = g_scratch;
    const int z = blockIdx.z;
    if (z < 4) {
        const float* A; const float* W; float* C; const float* bias;
        switch (z) {
            case 0: A = S + OFF_QF; W = W0;            C = S + OFF_QP; bias = b0;     break;
            case 1: A = S + OFF_KF; W = W0 + Hd * Hd;  C = S + OFF_KP; bias = nullptr;break;
            case 2: A = S + OFF_QF; W = Wv1;           C = S + OFF_QV; bias = bv1;    break;
            default:A = S + OFF_KF; W = Wv1 + Hd * Hd; C = S + OFF_KV; bias = nullptr;break;
        }
        int M = (z == 1 || z == 3) ? 1024 : 512;
        if (blockIdx.y * 16 >= M) return;
        gemm_tile16(A, W, bias, C, Hd, 0, blockIdx.y * 16, blockIdx.x * 64);
    } else {
        // transpose + fp16 round of W1, W2 into g_wt (Wt[n][k] row-major)
        int lin = blockIdx.y * 4 + blockIdx.x;      // 0..255
        if (lin >= 128) return;
        const float* W = (lin >= 64) ? W2 : W1;
        __half* oh = g_wt + (size_t)(lin >= 64 ? 1 : 0) * 65536;
        int base = (lin & 63) * 1024;
        #pragma unroll
        for (int t = 0; t < 4; t++) {
            int e = base + t * 256 + threadIdx.x;
            int n = e >> 8, k = e & 255;
            oh[e] = __float2half_rn(__ldg(W + (size_t)k * 256 + n));
        }
    }
}

// ---------------------------------------------------------------------------
// HMMA fused pair kernel: single-term fp16 GEMM, K=64 chunks, reg pipeline,
// A-build + variance INTERLEAVED into the layer-0 mainloop. (R15, unchanged)
// CTA = (b, q, 128 k-pairs). M=128, N=256, K=256. 256 threads, 8 warps 2Mx4N.
// ---------------------------------------------------------------------------
#define APITCH 264                       // fp16 elems per A row (528 B)
#define SM_AH 0
#define SM_W  (128 * APITCH * 2)         // 67584
#define WPITCH 144                       // bytes per W chunk row (64 fp16 + pad)
#define WBUF_BYTES (256 * WPITCH)        // 36864
#define SM_PART (SM_W + 2 * WBUF_BYTES)  // 141312
#define SMEM_TOTAL (SM_PART + 512 * 4)   // 143360

// load one k16-step of fragments (A rows + B cols) for this warp
__device__ __forceinline__ void load_step(uint32_t sbase, uint32_t wbuf,
                                          uint32_t a_rowoff, uint32_t b_rowoff,
                                          int kc, int ks,
                                          uint32_t afh[4][4], uint32_t bh[8][2])
{
    const uint32_t a_k = (uint32_t)(kc * 64 + ks * 16) * 2;
    const uint32_t b_k = (uint32_t)ks * 32;
    #pragma unroll
    for (int mi = 0; mi < 4; mi++)
        ldsm4(afh[mi], sbase + SM_AH + a_rowoff + (uint32_t)mi * 16 * (APITCH * 2) + a_k);
    #pragma unroll
    for (int np = 0; np < 4; np++) {
        uint32_t r[4];
        ldsm4(r, wbuf + b_rowoff + (uint32_t)np * 16 * WPITCH + b_k);
        bh[2*np][0] = r[0]; bh[2*np][1] = r[1];
        bh[2*np+1][0] = r[2]; bh[2*np+1][1] = r[3];
    }
}

// build A fp16 block: 64 columns starting at cb*64, all 128 rows.
__device__ __forceinline__ void build_a_block(char* smem,
                                              const float* __restrict__ qp,
                                              const float* __restrict__ kp,
                                              int tid, int cb)
{
    const int row = tid >> 1;
    const int c0  = cb * 64 + (tid & 1) * 32;
    const float* qpr = qp + c0;
    const float* kpr = kp + (size_t)row * Hd + c0;
    #pragma unroll
    for (int j4 = 0; j4 < 8; j4++) {
        float4 a  = ldg4(qpr + j4 * 4);
        float4 c  = ldg4(kpr + j4 * 4);
        uint32_t h0 = pack2h(frelu(a.x + c.x), frelu(a.y + c.y));
        uint32_t h1 = pack2h(frelu(a.z + c.z), frelu(a.w + c.w));
        uint32_t off = (uint32_t)row * (APITCH * 2) + (c0 + j4 * 4) * 2;
        *(uint2*)(smem + SM_AH + off) = make_uint2(h0, h1);
    }
}

__global__ void __launch_bounds__(256, 1)
pair_mma_kernel(const float* __restrict__ b1, const float* __restrict__ b2,
                const float* __restrict__ Wf, const float* __restrict__ bf,
                const float* __restrict__ Wv2, const float* __restrict__ bv2,
                float* __restrict__ out)
{
    extern __shared__ char smem[];
    const uint32_t sbase = smem_to_u32(smem);

    const int tid = threadIdx.x;
    const int w   = tid >> 5;
    const int wm  = w >> 2;            // 0..1 : M group (64 rows)
    const int wn  = w & 3;             // 0..3 : N group (64 cols)
    const int lt  = tid & 31;
    const int lrow = lt >> 2;          // 0..7
    const int lc2  = (lt & 3) * 2;     // 0,2,4,6

    const uint32_t a_rowoff = (uint32_t)(wm * 64 + (lt & 15)) * (APITCH * 2)
                            + (uint32_t)((lt >> 4) * 8) * 2;
    const uint32_t b_rowoff = (uint32_t)(wn * 64 + (lt & 7) + ((lt >> 4) & 1) * 8) * WPITCH
                            + (uint32_t)((lt >> 3) & 1) * 16;

    const int kb = blockIdx.x, q = blockIdx.y, b = blockIdx.z;
    const int qrow  = b * SQd + q;
    const int krow0 = b * SKd + kb * 128;

    const float* qp = g_scratch + OFF_QP + (size_t)qrow  * Hd;   // b0 pre-folded
    const float* kp = g_scratch + OFF_KP + (size_t)krow0 * Hd;
    const float* qv = g_scratch + OFF_QV + (size_t)qrow  * Hd;   // bv1 pre-folded
    const float* kv = g_scratch + OFF_KV + (size_t)krow0 * Hd;

    const int vrow  = tid >> 1;
    const int vpart = tid & 1;
    const float* qvr = qv + vpart * 128;
    const float* kvr = kv + (size_t)vrow * Hd + vpart * 128;
    const float* wvr = Wv2 + vpart * 128;
    float vacc = 0.f;

    // ---- prefetch W chunk 0 (layer 0) via cp.async: 256 rows x 128 B
    {
        #pragma unroll
        for (int it = 0; it < 8; it++) {
            int u = tid + it * 256;
            int n = u >> 3, j = u & 7;
            cp16(sbase + SM_W + n * WPITCH + j * 16, g_wt + n * 256 + j * 8);
        }
        CP_COMMIT();
    }

    // ---- build only A block 0; rest interleaved into mainloop
    build_a_block(smem, qp, kp, tid, 0);
    CP_WAIT0();
    __syncthreads();

    float c[4][8][4];
    uint32_t afh[2][4][4], bh[2][8][2];
    #pragma unroll
    for (int mi = 0; mi < 4; mi++)
        #pragma unroll
        for (int ni = 0; ni < 8; ni++)
            #pragma unroll
            for (int jj = 0; jj < 4; jj++) c[mi][ni][jj] = 0.f;

    // ================= layer 0: MMA interleaved with A-build + variance ====
    #pragma unroll 1
    for (int kc = 0; kc < 4; kc++) {
        const uint32_t wbuf = sbase + SM_W + (uint32_t)(kc & 1) * WBUF_BYTES;

        load_step(sbase, wbuf, a_rowoff, b_rowoff, kc, 0, afh[0], bh[0]);

        {
            const __half* Wh = g_wt + (size_t)((kc + 1) >> 2) * 65536;
            const int nkc = (kc + 1) & 3;
            const uint32_t dbase = sbase + SM_W + ((kc + 1) & 1) * WBUF_BYTES;
            #pragma unroll
            for (int it = 0; it < 8; it++) {
                int u = tid + it * 256;
                int n = u >> 3, j = u & 7;
                cp16(dbase + n * WPITCH + j * 16, Wh + n * 256 + nkc * 64 + j * 8);
            }
            CP_COMMIT();
        }

        #pragma unroll
        for (int ks = 0; ks < 4; ks++) {
            if (ks < 3)
                load_step(sbase, wbuf, a_rowoff, b_rowoff, kc, ks + 1,
                          afh[(ks + 1) & 1], bh[(ks + 1) & 1]);
            #pragma unroll
            for (int mi = 0; mi < 4; mi++)
                #pragma unroll
                for (int ni = 0; ni < 8; ni++)
                    mma_f32acc(c[mi][ni], afh[ks & 1][mi], bh[ks & 1][ni]);
        }

        if (kc < 3)
            build_a_block(smem, qp, kp, tid, kc + 1);

        #pragma unroll
        for (int j = 0; j < 8; j++) {
            int i = kc * 8 + j;
            float4 a = ldg4(qvr + i * 4);
            float4 cc = ldg4(kvr + i * 4);
            float4 ww = ldg4(wvr + i * 4);
            vacc = fmaf(frelu(a.x + cc.x), ww.x, vacc);
            vacc = fmaf(frelu(a.y + cc.y), ww.y, vacc);
            vacc = fmaf(frelu(a.z + cc.z), ww.z, vacc);
            vacc = fmaf(frelu(a.w + cc.w), ww.w, vacc);
        }
        if (kc == 3) {
            float s = vacc + __shfl_down_sync(0xffffffffu, vacc, 1);
            if (vpart == 0) {
                float x = s + __ldg(bv2);
                out[(size_t)Bsz * SQd * SKd + (size_t)qrow * SKd + kb * 128 + vrow] =
                    fmaxf(x, 0.f) + log1pf(expf(-fabsf(x)));
            }
        }

        CP_WAIT0();
        __syncthreads();
    }

    // ---- between layers: h1 = relu(D + b1) -> fp16 -> A SMEM; reset accum
    #pragma unroll
    for (int ni = 0; ni < 8; ni++) {
        int n = wn * 64 + ni * 8 + lc2;
        float2 bb = *(const float2*)(b1 + n);
        #pragma unroll
        for (int mi = 0; mi < 4; mi++) {
            int m1 = wm * 64 + mi * 16 + lrow;
            uint32_t off1 = (uint32_t)m1 * (APITCH * 2) + n * 2;
            *(uint32_t*)(smem + SM_AH + off1) =
                pack2h(frelu(c[mi][ni][0] + bb.x), frelu(c[mi][ni][1] + bb.y));
            uint32_t off2 = off1 + 8 * (APITCH * 2);
            *(uint32_t*)(smem + SM_AH + off2) =
                pack2h(frelu(c[mi][ni][2] + bb.x), frelu(c[mi][ni][3] + bb.y));
            c[mi][ni][0] = 0.f; c[mi][ni][1] = 0.f;
            c[mi][ni][2] = 0.f; c[mi][ni][3] = 0.f;
        }
    }
    __syncthreads();

    // ================= layer 1: pure MMA loop ================================
    #pragma unroll 1
    for (int kc = 0; kc < 4; kc++) {
        const int gg = 4 + kc;
        const uint32_t wbuf = sbase + SM_W + (uint32_t)(gg & 1) * WBUF_BYTES;

        load_step(sbase, wbuf, a_rowoff, b_rowoff, kc, 0, afh[0], bh[0]);

        if (gg + 1 < 8) {
            const __half* Wh = g_wt + 65536;
            const int nkc = (gg + 1) & 3;
            const uint32_t dbase = sbase + SM_W + ((gg + 1) & 1) * WBUF_BYTES;
            #pragma unroll
            for (int it = 0; it < 8; it++) {
                int u = tid + it * 256;
                int n = u >> 3, j = u & 7;
                cp16(dbase + n * WPITCH + j * 16, Wh + n * 256 + nkc * 64 + j * 8);
            }
            CP_COMMIT();
        }

        #pragma unroll
        for (int ks = 0; ks < 4; ks++) {
            if (ks < 3)
                load_step(sbase, wbuf, a_rowoff, b_rowoff, kc, ks + 1,
                          afh[(ks + 1) & 1], bh[(ks + 1) & 1]);
            #pragma unroll
            for (int mi = 0; mi < 4; mi++)
                #pragma unroll
                for (int ni = 0; ni < 8; ni++)
                    mma_f32acc(c[mi][ni], afh[ks & 1][mi], bh[ks & 1][ni]);
        }

        CP_WAIT0();
        __syncthreads();
    }

    // ---- final epilogue: logit = relu(D + b2) . Wf + bf
    float* part = (float*)(smem + SM_PART);
    float ps1[4], ps2[4];
    #pragma unroll
    for (int mi = 0; mi < 4; mi++) { ps1[mi] = 0.f; ps2[mi] = 0.f; }
    #pragma unroll
    for (int ni = 0; ni < 8; ni++) {
        int n = wn * 64 + ni * 8 + lc2;
        float2 bb = *(const float2*)(b2 + n);
        float2 wf = *(const float2*)(Wf + n);
        #pragma unroll
        for (int mi = 0; mi < 4; mi++) {
            ps1[mi] = fmaf(frelu(c[mi][ni][0] + bb.x), wf.x, ps1[mi]);
            ps1[mi] = fmaf(frelu(c[mi][ni][1] + bb.y), wf.y, ps1[mi]);
            ps2[mi] = fmaf(frelu(c[mi][ni][2] + bb.x), wf.x, ps2[mi]);
            ps2[mi] = fmaf(frelu(c[mi][ni][3] + bb.y), wf.y, ps2[mi]);
        }
    }
    #pragma unroll
    for (int mi = 0; mi < 4; mi++) {
        ps1[mi] += __shfl_xor_sync(0xffffffffu, ps1[mi], 1);
        ps1[mi] += __shfl_xor_sync(0xffffffffu, ps1[mi], 2);
        ps2[mi] += __shfl_xor_sync(0xffffffffu, ps2[mi], 1);
        ps2[mi] += __shfl_xor_sync(0xffffffffu, ps2[mi], 2);
    }
    if ((lt & 3) == 0) {
        #pragma unroll
        for (int mi = 0; mi < 4; mi++) {
            int m1 = wm * 64 + mi * 16 + lrow;
            part[wn * 128 + m1]     = ps1[mi];
            part[wn * 128 + m1 + 8] = ps2[mi];
        }
    }
    __syncthreads();
    if (tid < 128) {
        float s = part[tid] + part[128 + tid] + part[256 + tid] + part[384 + tid]
                + __ldg(bf);
        out[(size_t)qrow * SKd + kb * 128 + tid] = s;
    }
}

// ---------------------------------------------------------------------------
// Launch (3 launches per call)
// ---------------------------------------------------------------------------
extern "C" void kernel_launch(void* const* d_in, const int* in_sizes, int n_in,
                              void* d_out, int out_size)
{
    (void)in_sizes; (void)n_in; (void)out_size;
    const float* query = (const float*)d_in[0];
    const float* key_  = (const float*)d_in[1];
    const float* Wqe   = (const float*)d_in[2];
    const float* bqe   = (const float*)d_in[3];
    const float* Wke   = (const float*)d_in[4];
    const float* bke   = (const float*)d_in[5];
    const float* W0    = (const float*)d_in[6];
    const float* b0    = (const float*)d_in[7];
    const float* W1    = (const float*)d_in[8];
    const float* b1    = (const float*)d_in[9];
    const float* W2    = (const float*)d_in[10];
    const float* b2    = (const float*)d_in[11];
    const float* Wf    = (const float*)d_in[12];
    const float* bf    = (const float*)d_in[13];
    const float* Wv1   = (const float*)d_in[14];
    const float* bv1   = (const float*)d_in[15];
    const float* Wv2   = (const float*)d_in[16];
    const float* bv2   = (const float*)d_in[17];
    float* out = (float*)d_out;

    cudaFuncSetAttribute(pair_mma_kernel,
                         cudaFuncAttributeMaxDynamicSharedMemorySize, SMEM_TOTAL);

    // 1: encoders (qf, kf) — 16-row tiles, 384 CTAs
    encoder_kernel<<<dim3(4, 96), 256>>>(query, key_, Wqe, bqe, Wke, bke);
    // 2: projections (qp+b0, kp, qv+bv1, kv) + W1/W2 transpose (fp16)
    proj_trans_kernel<<<dim3(4, 64, 5), 256>>>(W0, Wv1, W1, W2, b0, bv1);
    // 3: fused HMMA pair MLP (single-term fp16, interleaved prologue)
    pair_mma_kernel<<<dim3(SKd / 128, SQd, Bsz), 256, SMEM_TOTAL>>>(
        b1, b2, Wf, bf, Wv2, bv2, out);
}

// round 17
// speedup vs baseline: 1.0351x; 1.0351x over previous
#include <cuda_runtime.h>
#include <cuda_fp16.h>
#include <math.h>
#include <cstdint>

// Problem constants
#define Bsz 2
#define SQd 256
#define SKd 512
#define Ed  512
#define Hd  256

#define NQ (Bsz*SQd)   // 512
#define NK (Bsz*SKd)   // 1024
#define OFF_QF 0
#define OFF_KF (OFF_QF + NQ*Hd)
#define OFF_QP (OFF_KF + NK*Hd)
#define OFF_KP (OFF_QP + NQ*Hd)
#define OFF_QV (OFF_KP + NK*Hd)
#define OFF_KV (OFF_QV + NQ*Hd)
#define SCRATCH_FLOATS (OFF_KV + NK*Hd)

__device__ float g_scratch[SCRATCH_FLOATS];
// Transposed fp16 weights: [W1h][W2h], each [256 n][256 k]
__device__ __align__(16) __half g_wt[2 * 256 * 256];

__device__ __forceinline__ float frelu(float x) { return x > 0.f ? x : 0.f; }
__device__ __forceinline__ float4 ldg4(const float* p) { return __ldg((const float4*)p); }

__device__ __forceinline__ uint32_t smem_to_u32(const void* p) {
    uint32_t a;
    asm("{ .reg .u64 t; cvta.to.shared.u64 t, %1; cvt.u32.u64 %0, t; }" : "=r"(a) : "l"(p));
    return a;
}
__device__ __forceinline__ void cp16(uint32_t dst, const void* src) {
    asm volatile("cp.async.cg.shared.global [%0], [%1], 16;" :: "r"(dst), "l"(src));
}
#define CP_COMMIT() asm volatile("cp.async.commit_group;" ::: "memory")
#define CP_WAIT0()  asm volatile("cp.async.wait_group 0;" ::: "memory")

// fp16 inputs, fp32 accumulate
__device__ __forceinline__ void mma_f32acc(float* c, const uint32_t* a, const uint32_t* b) {
    asm volatile(
        "mma.sync.aligned.m16n8k16.row.col.f32.f16.f16.f32 "
        "{%0,%1,%2,%3}, {%4,%5,%6,%7}, {%8,%9}, {%0,%1,%2,%3};"
        : "+f"(c[0]), "+f"(c[1]), "+f"(c[2]), "+f"(c[3])
        : "r"(a[0]), "r"(a[1]), "r"(a[2]), "r"(a[3]), "r"(b[0]), "r"(b[1]));
}
__device__ __forceinline__ void ldsm4(uint32_t* r, uint32_t addr) {
    asm volatile("ldmatrix.sync.aligned.m8n8.x4.shared.b16 {%0,%1,%2,%3}, [%4];"
                 : "=r"(r[0]), "=r"(r[1]), "=r"(r[2]), "=r"(r[3]) : "r"(addr));
}
// pack two fp32 -> fp16x2
__device__ __forceinline__ uint32_t pack2h(float x0, float x1) {
    __half2 p = __floats2half2_rn(x0, x1);
    return *reinterpret_cast<uint32_t*>(&p);
}

// ---------------------------------------------------------------------------
// Prep GEMM tile: cp.async double-buffered (R9/R15 proven). 256 threads, 32x64.
// ---------------------------------------------------------------------------
__device__ void gemm_tile(const float* __restrict__ A,
                          const float* __restrict__ W,
                          const float* __restrict__ bias,
                          float* __restrict__ C,
                          int K, int act, int row0, int col0)
{
    __shared__ float As[2][32 * 32];
    __shared__ float Ws[2][32 * 64];
    const int tid = threadIdx.x;
    const int tr  = tid >> 4;
    const int tc  = tid & 15;
    const uint32_t as0 = smem_to_u32(As);
    const uint32_t ws0 = smem_to_u32(Ws);

    const int lr  = tid >> 3;          // A loader: row 0..31
    const int lck = (tid & 7) * 4;     // A loader: col group

    // prefetch chunk 0
    cp16(as0 + (uint32_t)(lr * 32 + lck) * 4, A + (size_t)(row0 + lr) * K + lck);
    #pragma unroll
    for (int i = 0; i < 2; i++) {
        int f = tid + 256 * i; int k = f >> 4; int cc = (f & 15) * 4;
        cp16(ws0 + (uint32_t)(k * 64 + cc) * 4, W + (size_t)k * 256 + col0 + cc);
    }
    CP_COMMIT();

    float acc0x=0.f,acc0y=0.f,acc0z=0.f,acc0w=0.f,acc1x=0.f,acc1y=0.f,acc1z=0.f,acc1w=0.f;
    if (bias) {
        float4 bb = ldg4(bias + col0 + tc * 4);
        acc0x=bb.x;acc0y=bb.y;acc0z=bb.z;acc0w=bb.w;
        acc1x=bb.x;acc1y=bb.y;acc1z=bb.z;acc1w=bb.w;
    }

    const int nch = K >> 5;
    for (int g = 0; g < nch; g++) {
        CP_WAIT0();
        __syncthreads();
        if (g + 1 < nch) {
            int kc = (g + 1) * 32;
            uint32_t bsel = (uint32_t)((g + 1) & 1);
            cp16(as0 + bsel * 4096 + (uint32_t)(lr * 32 + lck) * 4,
                 A + (size_t)(row0 + lr) * K + kc + lck);
            #pragma unroll
            for (int i = 0; i < 2; i++) {
                int f = tid + 256 * i; int k = f >> 4; int cc = (f & 15) * 4;
                cp16(ws0 + bsel * 8192 + (uint32_t)(k * 64 + cc) * 4,
                     W + (size_t)(kc + k) * 256 + col0 + cc);
            }
            CP_COMMIT();
        }
        const float* Asb = As[g & 1];
        const float* Wsb = Ws[g & 1];
        #pragma unroll 8
        for (int k = 0; k < 32; k++) {
            float a0 = Asb[(tr * 2) * 32 + k];
            float a1 = Asb[(tr * 2 + 1) * 32 + k];
            float4 w = *(const float4*)(Wsb + k * 64 + tc * 4);
            acc0x = fmaf(a0, w.x, acc0x); acc0y = fmaf(a0, w.y, acc0y);
            acc0z = fmaf(a0, w.z, acc0z); acc0w = fmaf(a0, w.w, acc0w);
            acc1x = fmaf(a1, w.x, acc1x); acc1y = fmaf(a1, w.y, acc1y);
            acc1z = fmaf(a1, w.z, acc1z); acc1w = fmaf(a1, w.w, acc1w);
        }
    }
    if (act) {
        acc0x=frelu(acc0x);acc0y=frelu(acc0y);acc0z=frelu(acc0z);acc0w=frelu(acc0w);
        acc1x=frelu(acc1x);acc1y=frelu(acc1y);acc1z=frelu(acc1z);acc1w=frelu(acc1w);
    }
    *(float4*)(C + (size_t)(row0+tr*2)  *256 + col0 + tc*4) = make_float4(acc0x,acc0y,acc0z,acc0w);
    *(float4*)(C + (size_t)(row0+tr*2+1)*256 + col0 + tc*4) = make_float4(acc1x,acc1y,acc1z,acc1w);
}

// Launch 1: both encoders. grid (4, 48)
__global__ void encoder_kernel(const float* __restrict__ query,
                               const float* __restrict__ key_,
                               const float* __restrict__ Wqe, const float* __restrict__ bqe,
                               const float* __restrict__ Wke, const float* __restrict__ bke)
{
    float* S = g_scratch;
    int y = blockIdx.y;
    if (y < 16)
        gemm_tile(query, Wqe, bqe, S + OFF_QF, Ed, 1, y * 32, blockIdx.x * 64);
    else
        gemm_tile(key_,  Wke, bke, S + OFF_KF, Ed, 1, (y - 16) * 32, blockIdx.x * 64);
}

// Launch 2: 4 projections (b0 folded into qp, bv1 into qv) + W transpose (fp16).
// grid (4, 32, 5)
__global__ void proj_trans_kernel(const float* __restrict__ W0,
                                  const float* __restrict__ Wv1,
                                  const float* __restrict__ W1,
                                  const float* __restrict__ W2,
                                  const float* __restrict__ b0,
                                  const float* __restrict__ bv1)
{
    float* S = g_scratch;
    const int z = blockIdx.z;
    if (z < 4) {
        const float* A; const float* W; float* C; const float* bias;
        switch (z) {
            case 0: A = S + OFF_QF; W = W0;            C = S + OFF_QP; bias = b0;     break;
            case 1: A = S + OFF_KF; W = W0 + Hd * Hd;  C = S + OFF_KP; bias = nullptr;break;
            case 2: A = S + OFF_QF; W = Wv1;           C = S + OFF_QV; bias = bv1;    break;
            default:A = S + OFF_KF; W = Wv1 + Hd * Hd; C = S + OFF_KV; bias = nullptr;break;
        }
        int M = (z == 1 || z == 3) ? 1024 : 512;
        if (blockIdx.y * 32 >= M) return;
        gemm_tile(A, W, bias, C, Hd, 0, blockIdx.y * 32, blockIdx.x * 64);
    } else {
        // transpose + fp16 round of W1, W2 into g_wt (Wt[n][k] row-major)
        int lin = blockIdx.y * 4 + blockIdx.x;      // 0..127
        const float* W = (lin >= 64) ? W2 : W1;
        __half* oh = g_wt + (size_t)(lin >= 64 ? 1 : 0) * 65536;
        int base = (lin & 63) * 1024;
        #pragma unroll
        for (int t = 0; t < 4; t++) {
            int e = base + t * 256 + threadIdx.x;
            int n = e >> 8, k = e & 255;
            oh[e] = __float2half_rn(__ldg(W + (size_t)k * 256 + n));
        }
    }
}

// ---------------------------------------------------------------------------
// HMMA fused pair kernel: single-term fp16 GEMM, K=64 chunks, reg pipeline,
// A-build + variance INTERLEAVED into the layer-0 mainloop. (R15 + dead-sync
// removal at the end of layer 1.)
// CTA = (b, q, 128 k-pairs). M=128, N=256, K=256. 256 threads, 8 warps 2Mx4N.
// ---------------------------------------------------------------------------
#define APITCH 264                       // fp16 elems per A row (528 B)
#define SM_AH 0
#define SM_W  (128 * APITCH * 2)         // 67584
#define WPITCH 144                       // bytes per W chunk row (64 fp16 + pad)
#define WBUF_BYTES (256 * WPITCH)        // 36864
#define SM_PART (SM_W + 2 * WBUF_BYTES)  // 141312
#define SMEM_TOTAL (SM_PART + 512 * 4)   // 143360

// load one k16-step of fragments (A rows + B cols) for this warp
__device__ __forceinline__ void load_step(uint32_t sbase, uint32_t wbuf,
                                          uint32_t a_rowoff, uint32_t b_rowoff,
                                          int kc, int ks,
                                          uint32_t afh[4][4], uint32_t bh[8][2])
{
    const uint32_t a_k = (uint32_t)(kc * 64 + ks * 16) * 2;
    const uint32_t b_k = (uint32_t)ks * 32;
    #pragma unroll
    for (int mi = 0; mi < 4; mi++)
        ldsm4(afh[mi], sbase + SM_AH + a_rowoff + (uint32_t)mi * 16 * (APITCH * 2) + a_k);
    #pragma unroll
    for (int np = 0; np < 4; np++) {
        uint32_t r[4];
        ldsm4(r, wbuf + b_rowoff + (uint32_t)np * 16 * WPITCH + b_k);
        bh[2*np][0] = r[0]; bh[2*np][1] = r[1];
        bh[2*np+1][0] = r[2]; bh[2*np+1][1] = r[3];
    }
}

// build A fp16 block: 64 columns starting at cb*64, all 128 rows.
__device__ __forceinline__ void build_a_block(char* smem,
                                              const float* __restrict__ qp,
                                              const float* __restrict__ kp,
                                              int tid, int cb)
{
    const int row = tid >> 1;
    const int c0  = cb * 64 + (tid & 1) * 32;
    const float* qpr = qp + c0;
    const float* kpr = kp + (size_t)row * Hd + c0;
    #pragma unroll
    for (int j4 = 0; j4 < 8; j4++) {
        float4 a  = ldg4(qpr + j4 * 4);
        float4 c  = ldg4(kpr + j4 * 4);
        uint32_t h0 = pack2h(frelu(a.x + c.x), frelu(a.y + c.y));
        uint32_t h1 = pack2h(frelu(a.z + c.z), frelu(a.w + c.w));
        uint32_t off = (uint32_t)row * (APITCH * 2) + (c0 + j4 * 4) * 2;
        *(uint2*)(smem + SM_AH + off) = make_uint2(h0, h1);
    }
}

__global__ void __launch_bounds__(256, 1)
pair_mma_kernel(const float* __restrict__ b1, const float* __restrict__ b2,
                const float* __restrict__ Wf, const float* __restrict__ bf,
                const float* __restrict__ Wv2, const float* __restrict__ bv2,
                float* __restrict__ out)
{
    extern __shared__ char smem[];
    const uint32_t sbase = smem_to_u32(smem);

    const int tid = threadIdx.x;
    const int w   = tid >> 5;
    const int wm  = w >> 2;            // 0..1 : M group (64 rows)
    const int wn  = w & 3;             // 0..3 : N group (64 cols)
    const int lt  = tid & 31;
    const int lrow = lt >> 2;          // 0..7
    const int lc2  = (lt & 3) * 2;     // 0,2,4,6

    const uint32_t a_rowoff = (uint32_t)(wm * 64 + (lt & 15)) * (APITCH * 2)
                            + (uint32_t)((lt >> 4) * 8) * 2;
    const uint32_t b_rowoff = (uint32_t)(wn * 64 + (lt & 7) + ((lt >> 4) & 1) * 8) * WPITCH
                            + (uint32_t)((lt >> 3) & 1) * 16;

    const int kb = blockIdx.x, q = blockIdx.y, b = blockIdx.z;
    const int qrow  = b * SQd + q;
    const int krow0 = b * SKd + kb * 128;

    const float* qp = g_scratch + OFF_QP + (size_t)qrow  * Hd;   // b0 pre-folded
    const float* kp = g_scratch + OFF_KP + (size_t)krow0 * Hd;
    const float* qv = g_scratch + OFF_QV + (size_t)qrow  * Hd;   // bv1 pre-folded
    const float* kv = g_scratch + OFF_KV + (size_t)krow0 * Hd;

    const int vrow  = tid >> 1;
    const int vpart = tid & 1;
    const float* qvr = qv + vpart * 128;
    const float* kvr = kv + (size_t)vrow * Hd + vpart * 128;
    const float* wvr = Wv2 + vpart * 128;
    float vacc = 0.f;

    // ---- prefetch W chunk 0 (layer 0) via cp.async: 256 rows x 128 B
    {
        #pragma unroll
        for (int it = 0; it < 8; it++) {
            int u = tid + it * 256;
            int n = u >> 3, j = u & 7;
            cp16(sbase + SM_W + n * WPITCH + j * 16, g_wt + n * 256 + j * 8);
        }
        CP_COMMIT();
    }

    // ---- build only A block 0; rest interleaved into mainloop
    build_a_block(smem, qp, kp, tid, 0);
    CP_WAIT0();
    __syncthreads();

    float c[4][8][4];
    uint32_t afh[2][4][4], bh[2][8][2];
    #pragma unroll
    for (int mi = 0; mi < 4; mi++)
        #pragma unroll
        for (int ni = 0; ni < 8; ni++)
            #pragma unroll
            for (int jj = 0; jj < 4; jj++) c[mi][ni][jj] = 0.f;

    // ================= layer 0: MMA interleaved with A-build + variance ====
    #pragma unroll 1
    for (int kc = 0; kc < 4; kc++) {
        const uint32_t wbuf = sbase + SM_W + (uint32_t)(kc & 1) * WBUF_BYTES;

        load_step(sbase, wbuf, a_rowoff, b_rowoff, kc, 0, afh[0], bh[0]);

        {
            const __half* Wh = g_wt + (size_t)((kc + 1) >> 2) * 65536;
            const int nkc = (kc + 1) & 3;
            const uint32_t dbase = sbase + SM_W + ((kc + 1) & 1) * WBUF_BYTES;
            #pragma unroll
            for (int it = 0; it < 8; it++) {
                int u = tid + it * 256;
                int n = u >> 3, j = u & 7;
                cp16(dbase + n * WPITCH + j * 16, Wh + n * 256 + nkc * 64 + j * 8);
            }
            CP_COMMIT();
        }

        #pragma unroll
        for (int ks = 0; ks < 4; ks++) {
            if (ks < 3)
                load_step(sbase, wbuf, a_rowoff, b_rowoff, kc, ks + 1,
                          afh[(ks + 1) & 1], bh[(ks + 1) & 1]);
            #pragma unroll
            for (int mi = 0; mi < 4; mi++)
                #pragma unroll
                for (int ni = 0; ni < 8; ni++)
                    mma_f32acc(c[mi][ni], afh[ks & 1][mi], bh[ks & 1][ni]);
        }

        if (kc < 3)
            build_a_block(smem, qp, kp, tid, kc + 1);

        #pragma unroll
        for (int j = 0; j < 8; j++) {
            int i = kc * 8 + j;
            float4 a = ldg4(qvr + i * 4);
            float4 cc = ldg4(kvr + i * 4);
            float4 ww = ldg4(wvr + i * 4);
            vacc = fmaf(frelu(a.x + cc.x), ww.x, vacc);
            vacc = fmaf(frelu(a.y + cc.y), ww.y, vacc);
            vacc = fmaf(frelu(a.z + cc.z), ww.z, vacc);
            vacc = fmaf(frelu(a.w + cc.w), ww.w, vacc);
        }
        if (kc == 3) {
            float s = vacc + __shfl_down_sync(0xffffffffu, vacc, 1);
            if (vpart == 0) {
                float x = s + __ldg(bv2);
                out[(size_t)Bsz * SQd * SKd + (size_t)qrow * SKd + kb * 128 + vrow] =
                    fmaxf(x, 0.f) + log1pf(expf(-fabsf(x)));
            }
        }

        CP_WAIT0();
        __syncthreads();
    }

    // ---- between layers: h1 = relu(D + b1) -> fp16 -> A SMEM; reset accum
    #pragma unroll
    for (int ni = 0; ni < 8; ni++) {
        int n = wn * 64 + ni * 8 + lc2;
        float2 bb = *(const float2*)(b1 + n);
        #pragma unroll
        for (int mi = 0; mi < 4; mi++) {
            int m1 = wm * 64 + mi * 16 + lrow;
            uint32_t off1 = (uint32_t)m1 * (APITCH * 2) + n * 2;
            *(uint32_t*)(smem + SM_AH + off1) =
                pack2h(frelu(c[mi][ni][0] + bb.x), frelu(c[mi][ni][1] + bb.y));
            uint32_t off2 = off1 + 8 * (APITCH * 2);
            *(uint32_t*)(smem + SM_AH + off2) =
                pack2h(frelu(c[mi][ni][2] + bb.x), frelu(c[mi][ni][3] + bb.y));
            c[mi][ni][0] = 0.f; c[mi][ni][1] = 0.f;
            c[mi][ni][2] = 0.f; c[mi][ni][3] = 0.f;
        }
    }
    __syncthreads();

    // ================= layer 1: pure MMA loop ================================
    #pragma unroll 1
    for (int kc = 0; kc < 4; kc++) {
        const int gg = 4 + kc;
        const uint32_t wbuf = sbase + SM_W + (uint32_t)(gg & 1) * WBUF_BYTES;

        load_step(sbase, wbuf, a_rowoff, b_rowoff, kc, 0, afh[0], bh[0]);

        if (gg + 1 < 8) {
            const __half* Wh = g_wt + 65536;
            const int nkc = (gg + 1) & 3;
            const uint32_t dbase = sbase + SM_W + ((gg + 1) & 1) * WBUF_BYTES;
            #pragma unroll
            for (int it = 0; it < 8; it++) {
                int u = tid + it * 256;
                int n = u >> 3, j = u & 7;
                cp16(dbase + n * WPITCH + j * 16, Wh + n * 256 + nkc * 64 + j * 8);
            }
            CP_COMMIT();
        }

        #pragma unroll
        for (int ks = 0; ks < 4; ks++) {
            if (ks < 3)
                load_step(sbase, wbuf, a_rowoff, b_rowoff, kc, ks + 1,
                          afh[(ks + 1) & 1], bh[(ks + 1) & 1]);
            #pragma unroll
            for (int mi = 0; mi < 4; mi++)
                #pragma unroll
                for (int ni = 0; ni < 8; ni++)
                    mma_f32acc(c[mi][ni], afh[ks & 1][mi], bh[ks & 1][ni]);
        }

        // last chunk: no outstanding cp.async, epilogue has its own barrier
        // before cross-warp reads -> skip the dead wait+sync at gg == 7
        if (kc < 3) {
            CP_WAIT0();
            __syncthreads();
        }
    }

    // ---- final epilogue: logit = relu(D + b2) . Wf + bf
    float* part = (float*)(smem + SM_PART);
    float ps1[4], ps2[4];
    #pragma unroll
    for (int mi = 0; mi < 4; mi++) { ps1[mi] = 0.f; ps2[mi] = 0.f; }
    #pragma unroll
    for (int ni = 0; ni < 8; ni++) {
        int n = wn * 64 + ni * 8 + lc2;
        float2 bb = *(const float2*)(b2 + n);
        float2 wf = *(const float2*)(Wf + n);
        #pragma unroll
        for (int mi = 0; mi < 4; mi++) {
            ps1[mi] = fmaf(frelu(c[mi][ni][0] + bb.x), wf.x, ps1[mi]);
            ps1[mi] = fmaf(frelu(c[mi][ni][1] + bb.y), wf.y, ps1[mi]);
            ps2[mi] = fmaf(frelu(c[mi][ni][2] + bb.x), wf.x, ps2[mi]);
            ps2[mi] = fmaf(frelu(c[mi][ni][3] + bb.y), wf.y, ps2[mi]);
        }
    }
    #pragma unroll
    for (int mi = 0; mi < 4; mi++) {
        ps1[mi] += __shfl_xor_sync(0xffffffffu, ps1[mi], 1);
        ps1[mi] += __shfl_xor_sync(0xffffffffu, ps1[mi], 2);
        ps2[mi] += __shfl_xor_sync(0xffffffffu, ps2[mi], 1);
        ps2[mi] += __shfl_xor_sync(0xffffffffu, ps2[mi], 2);
    }
    if ((lt & 3) == 0) {
        #pragma unroll
        for (int mi = 0; mi < 4; mi++) {
            int m1 = wm * 64 + mi * 16 + lrow;
            part[wn * 128 + m1]     = ps1[mi];
            part[wn * 128 + m1 + 8] = ps2[mi];
        }
    }
    __syncthreads();
    if (tid < 128) {
        float s = part[tid] + part[128 + tid] + part[256 + tid] + part[384 + tid]
                + __ldg(bf);
        out[(size_t)qrow * SKd + kb * 128 + tid] = s;
    }
}

// ---------------------------------------------------------------------------
// Launch (3 launches per call)
// ---------------------------------------------------------------------------
extern "C" void kernel_launch(void* const* d_in, const int* in_sizes, int n_in,
                              void* d_out, int out_size)
{
    (void)in_sizes; (void)n_in; (void)out_size;
    const float* query = (const float*)d_in[0];
    const float* key_  = (const float*)d_in[1];
    const float* Wqe   = (const float*)d_in[2];
    const float* bqe   = (const float*)d_in[3];
    const float* Wke   = (const float*)d_in[4];
    const float* bke   = (const float*)d_in[5];
    const float* W0    = (const float*)d_in[6];
    const float* b0    = (const float*)d_in[7];
    const float* W1    = (const float*)d_in[8];
    const float* b1    = (const float*)d_in[9];
    const float* W2    = (const float*)d_in[10];
    const float* b2    = (const float*)d_in[11];
    const float* Wf    = (const float*)d_in[12];
    const float* bf    = (const float*)d_in[13];
    const float* Wv1   = (const float*)d_in[14];
    const float* bv1   = (const float*)d_in[15];
    const float* Wv2   = (const float*)d_in[16];
    const float* bv2   = (const float*)d_in[17];
    float* out = (float*)d_out;

    cudaFuncSetAttribute(pair_mma_kernel,
                         cudaFuncAttributeMaxDynamicSharedMemorySize, SMEM_TOTAL);

    // 1: encoders (qf, kf) — 32-row tiles (R15 proven config)
    encoder_kernel<<<dim3(4, 48), 256>>>(query, key_, Wqe, bqe, Wke, bke);
    // 2: projections (qp+b0, kp, qv+bv1, kv) + W1/W2 transpose (fp16)
    proj_trans_kernel<<<dim3(4, 32, 5), 256>>>(W0, Wv1, W1, W2, b0, bv1);
    // 3: fused HMMA pair MLP (single-term fp16, interleaved prologue)
    pair_mma_kernel<<<dim3(SKd / 128, SQd, Bsz), 256, SMEM_TOTAL>>>(
        b1, b2, Wf, bf, Wv2, bv2, out);
}